// round 10
// baseline (speedup 1.0000x reference)
#include <cuda_runtime.h>
#include <cuda_bf16.h>
#include <cstdint>
#include <cstddef>

// ---------------------------------------------------------------------------
// DGCNN pipeline. B=8, N=2048, K=20.
// Round 10: warp radix-select (4x8-bit MSB passes + ballot emission) replaces
// the 20-pass iterative argmin in knn select. Neighbor SET identical (ties by
// lowest index; order irrelevant downstream). Rest as round 9.
// ---------------------------------------------------------------------------

#define NPTS   2048
#define NB     8
#define NROWS  (NB*NPTS)   // 16384
#define KNN    20
#define FINF   3.4e38f

// ------------------------- device scratch (no allocs) ----------------------
__device__ float  g_gram[(size_t)NB * NPTS * NPTS];   // reused per layer
__device__ float  g_hh[(size_t)NROWS * 512];          // [rows x 2O], hc | hn
__device__ float  g_hm[(size_t)NROWS * 1024];         // seq features
__device__ float  g_hmax[(size_t)NROWS * 256];
__device__ float  g_hmin[(size_t)NROWS * 256];
__device__ float  g_sq[NROWS];
__device__ int    g_idx[(size_t)NROWS * KNN];
__device__ float  g_wtmp[3 * 128];                    // layer-1 fp32 weights
__device__ float  g_part[(size_t)NROWS * 32];         // per-row group partials
__device__ float  g_mu[128];
__device__ float  g_rs[128];
__device__ float  g_pmax[NB * 8 * 1024];              // seq max partials
__device__ float  g_gvec[NB * 1024];
// bf16 split operands
__device__ __align__(16) __nv_bfloat16 g_ch[(size_t)NROWS * 512];   // concat hi
__device__ __align__(16) __nv_bfloat16 g_cl[(size_t)NROWS * 512];   // concat lo
__device__ __align__(16) __nv_bfloat16 g_wth[512 * 128];            // wtmp^T hi [2O][C]
__device__ __align__(16) __nv_bfloat16 g_wtl[512 * 128];            // wtmp^T lo
__device__ __align__(16) __nv_bfloat16 g_wmh[1024 * 512];           // wm hi
__device__ __align__(16) __nv_bfloat16 g_wml[1024 * 512];           // wm lo

__device__ __forceinline__ float leaky02(float v) { return v > 0.f ? v : 0.2f * v; }

__device__ __forceinline__ void split_bf16(float v, __nv_bfloat16& h, __nv_bfloat16& l) {
    h = __float2bfloat16(v);
    l = __float2bfloat16(v - __bfloat162float(h));
}

// --------------------------- cp.async helpers -------------------------------
__device__ __forceinline__ void cp16(void* smem, const void* g) {
    uint32_t s = (uint32_t)__cvta_generic_to_shared(smem);
    asm volatile("cp.async.cg.shared.global [%0], [%1], 16;" :: "r"(s), "l"(g));
}
__device__ __forceinline__ void cp_commit() {
    asm volatile("cp.async.commit_group;");
}
template <int N>
__device__ __forceinline__ void cp_wait() {
    asm volatile("cp.async.wait_group %0;" :: "n"(N));
}

// ------------------------------ sq kernel (layer 1 only) -------------------
__global__ void sq_kernel(const float* __restrict__ X) {
    int r = blockIdx.x * 256 + threadIdx.x;
    if (r < NROWS) {
        float a = X[r * 3], b = X[r * 3 + 1], c = X[r * 3 + 2];
        g_sq[r] = a * a + b * b + c * c;
    }
}

// ================= tensor-core GEMM: pre-split bf16, fp32 accum =============
__device__ __forceinline__ void mma16816(float c[4], const uint32_t a[4],
                                         const uint32_t b[2]) {
    asm volatile(
        "mma.sync.aligned.m16n8k16.row.col.f32.bf16.bf16.f32 "
        "{%0,%1,%2,%3}, {%4,%5,%6,%7}, {%8,%9}, {%0,%1,%2,%3};\n"
        : "+f"(c[0]), "+f"(c[1]), "+f"(c[2]), "+f"(c[3])
        : "r"(a[0]), "r"(a[1]), "r"(a[2]), "r"(a[3]), "r"(b[0]), "r"(b[1]));
}

#define SMS 40                 // smem k-stride in u16 (32 + 8 pad, conflict-free)
#define STAGE_U16 (4 * 128 * SMS)   // Ah|Al|Bh|Bl per stage
#define GEMM_SMEM (2 * STAGE_U16 * 2)  // bytes: 81920

template <bool SYM>
__global__ __launch_bounds__(256, 2) void mmagemm_bf(
    const __nv_bfloat16* __restrict__ pAh, const __nv_bfloat16* __restrict__ pAl,
    int lda, size_t sA,
    const __nv_bfloat16* __restrict__ pBh, const __nv_bfloat16* __restrict__ pBl,
    int ldb, size_t sB,
    float* __restrict__ Cp, int ldc, size_t sC, int K)
{
    extern __shared__ __align__(16) uint16_t dyn[];
    const __nv_bfloat16* Abh = pAh + (size_t)blockIdx.z * sA;
    const __nv_bfloat16* Abl = pAl + (size_t)blockIdx.z * sA;
    const __nv_bfloat16* Bbh = pBh + (size_t)blockIdx.z * sB;
    const __nv_bfloat16* Bbl = pBl + (size_t)blockIdx.z * sB;
    float* Cb = Cp + (size_t)blockIdx.z * sC;

    int m0, n0;
    if (SYM) {
        int i = blockIdx.x;
        int bx = (int)((sqrtf(8.f * (float)i + 1.f) - 1.f) * 0.5f);
        while ((bx + 1) * (bx + 2) / 2 <= i) bx++;
        while (bx * (bx + 1) / 2 > i) bx--;
        int by = i - bx * (bx + 1) / 2;
        m0 = by * 128; n0 = bx * 128;
    } else {
        m0 = blockIdx.y * 128; n0 = blockIdx.x * 128;
    }

    const int tid = threadIdx.x;
    const int warp = tid >> 5, lane = tid & 31;
    const int wrm = warp >> 1, wrn = warp & 1;
    const int g = lane >> 2, q = lane & 3;
    const int row = tid >> 1, c0 = (tid & 1) * 16;

    float acc[2][8][4];
#pragma unroll
    for (int mt = 0; mt < 2; mt++)
#pragma unroll
        for (int nt = 0; nt < 8; nt++)
#pragma unroll
            for (int j = 0; j < 4; j++) acc[mt][nt][j] = 0.f;

    const int nk = K >> 5;

    auto load_stage = [&](int st, int k0) {
        uint16_t* S  = dyn + st * STAGE_U16;
        uint16_t* Ah = S;
        uint16_t* Al = S + 128 * SMS;
        uint16_t* Bh = S + 2 * 128 * SMS;
        uint16_t* Bl = S + 3 * 128 * SMS;
        const size_t aoff = (size_t)(m0 + row) * lda + k0 + c0;
        const size_t boff = (size_t)(n0 + row) * ldb + k0 + c0;
        cp16(&Ah[row * SMS + c0],     &Abh[aoff]);
        cp16(&Ah[row * SMS + c0 + 8], &Abh[aoff + 8]);
        cp16(&Al[row * SMS + c0],     &Abl[aoff]);
        cp16(&Al[row * SMS + c0 + 8], &Abl[aoff + 8]);
        cp16(&Bh[row * SMS + c0],     &Bbh[boff]);
        cp16(&Bh[row * SMS + c0 + 8], &Bbh[boff + 8]);
        cp16(&Bl[row * SMS + c0],     &Bbl[boff]);
        cp16(&Bl[row * SMS + c0 + 8], &Bbl[boff + 8]);
        cp_commit();
    };

    load_stage(0, 0);

    for (int kc = 0; kc < nk; kc++) {
        if (kc + 1 < nk) {
            load_stage((kc + 1) & 1, (kc + 1) << 5);
            cp_wait<1>();
        } else {
            cp_wait<0>();
        }
        __syncthreads();

        uint16_t* S  = dyn + (kc & 1) * STAGE_U16;
        uint16_t* Ah = S;
        uint16_t* Al = S + 128 * SMS;
        uint16_t* Bh = S + 2 * 128 * SMS;
        uint16_t* Bl = S + 3 * 128 * SMS;

#pragma unroll
        for (int ks = 0; ks < 32; ks += 16) {
            const int cb = ks + q * 2;
            uint32_t afh[2][4], afl[2][4];
#pragma unroll
            for (int mt = 0; mt < 2; mt++) {
                int r = wrm * 32 + mt * 16 + g;
                afh[mt][0] = *(const uint32_t*)&Ah[r * SMS + cb];
                afh[mt][1] = *(const uint32_t*)&Ah[(r + 8) * SMS + cb];
                afh[mt][2] = *(const uint32_t*)&Ah[r * SMS + cb + 8];
                afh[mt][3] = *(const uint32_t*)&Ah[(r + 8) * SMS + cb + 8];
                afl[mt][0] = *(const uint32_t*)&Al[r * SMS + cb];
                afl[mt][1] = *(const uint32_t*)&Al[(r + 8) * SMS + cb];
                afl[mt][2] = *(const uint32_t*)&Al[r * SMS + cb + 8];
                afl[mt][3] = *(const uint32_t*)&Al[(r + 8) * SMS + cb + 8];
            }
#pragma unroll
            for (int nt = 0; nt < 8; nt++) {
                int n = wrn * 64 + nt * 8 + g;
                uint32_t bfh[2], bfl[2];
                bfh[0] = *(const uint32_t*)&Bh[n * SMS + cb];
                bfh[1] = *(const uint32_t*)&Bh[n * SMS + cb + 8];
                bfl[0] = *(const uint32_t*)&Bl[n * SMS + cb];
                bfl[1] = *(const uint32_t*)&Bl[n * SMS + cb + 8];
#pragma unroll
                for (int mt = 0; mt < 2; mt++) {
                    mma16816(acc[mt][nt], afh[mt], bfh);
                    mma16816(acc[mt][nt], afh[mt], bfl);
                    mma16816(acc[mt][nt], afl[mt], bfh);
                }
            }
        }
        __syncthreads();
    }

#pragma unroll
    for (int mt = 0; mt < 2; mt++) {
        int r0 = m0 + wrm * 32 + mt * 16 + g;
#pragma unroll
        for (int nt = 0; nt < 8; nt++) {
            int cc = n0 + wrn * 64 + nt * 8 + q * 2;
            *(float2*)&Cb[(size_t)r0 * ldc + cc] =
                make_float2(acc[mt][nt][0], acc[mt][nt][1]);
            *(float2*)&Cb[(size_t)(r0 + 8) * ldc + cc] =
                make_float2(acc[mt][nt][2], acc[mt][nt][3]);
            if (SYM && n0 != m0) {
                Cb[(size_t)cc * ldc + r0]           = acc[mt][nt][0];
                Cb[(size_t)(cc + 1) * ldc + r0]     = acc[mt][nt][1];
                Cb[(size_t)cc * ldc + r0 + 8]       = acc[mt][nt][2];
                Cb[(size_t)(cc + 1) * ldc + r0 + 8] = acc[mt][nt][3];
            }
        }
    }
}

// ==================== warp radix-select top-20 (set semantics) ==============
// Keys: order-preserving uint map of fp32 distance. 4 MSB-first 8-bit passes
// over a 256-bucket smem histogram locate the exact 20th-smallest key; a
// ballot/popc emission writes all strictly-smaller indices plus equal keys
// filled by lowest index (== jax top_k tie rule; order irrelevant downstream).
__device__ __forceinline__ uint32_t fkey(float d) {
    uint32_t b = __float_as_uint(d);
    return (b & 0x80000000u) ? ~b : (b | 0x80000000u);
}

__device__ __forceinline__ void radix_topk(uint32_t* u, uint32_t* h,
                                           int row, int lane) {
    const unsigned FULL = 0xffffffffu;
    uint32_t prefix = 0, pmask = 0;
    int k = KNN;
#pragma unroll
    for (int pass = 0; pass < 4; pass++) {
        const int shift = 24 - 8 * pass;
        // zero histogram
#pragma unroll
        for (int i = 0; i < 8; i++) h[lane + 32 * i] = 0;
        __syncwarp();
        // count
#pragma unroll 8
        for (int j = 0; j < 64; j++) {
            uint32_t key = u[lane + 32 * j];
            if ((key & pmask) == prefix)
                atomicAdd(&h[(key >> shift) & 255], 1u);
        }
        __syncwarp();
        // lane owns buckets [8*lane, 8*lane+8)
        uint32_t c[8]; int s = 0;
#pragma unroll
        for (int i = 0; i < 8; i++) { c[i] = h[lane * 8 + i]; s += c[i]; }
        int pre = s;
#pragma unroll
        for (int off = 1; off < 32; off <<= 1) {
            int nv = __shfl_up_sync(FULL, pre, off);
            if (lane >= off) pre += nv;
        }
        int excl = pre - s;
        bool has = (k > excl) && (k <= pre);
        int bg = 0, kn = 0;
        if (has) {
            int cum = excl, bsel = -1;
#pragma unroll
            for (int i = 0; i < 8; i++) {
                if (bsel < 0 && k <= cum + (int)c[i]) { bsel = i; kn = k - cum; }
                cum += (int)c[i];
            }
            bg = lane * 8 + bsel;
        }
        unsigned bal = __ballot_sync(FULL, has);
        int wl = __ffs(bal) - 1;
        bg = __shfl_sync(FULL, bg, wl);
        k  = __shfl_sync(FULL, kn, wl);
        prefix |= (uint32_t)bg << shift;
        pmask  |= 0xFFu << shift;
        __syncwarp();
    }
    const uint32_t ustar = prefix;   // exact kth-smallest key; k = equals needed
    const unsigned ltmask = (1u << lane) - 1u;
    // emit strict-less (exactly KNN - k of them)
    int base = 0;
#pragma unroll 4
    for (int j = 0; j < 64; j++) {
        int m = lane + 32 * j;
        bool less = u[m] < ustar;
        unsigned bal = __ballot_sync(FULL, less);
        if (less) g_idx[(size_t)row * KNN + base + __popc(bal & ltmask)] = m;
        base += __popc(bal);
    }
    // fill remaining k slots with equal keys, lowest index first
    for (int j = 0; j < 64 && base < KNN; j++) {
        int m = lane + 32 * j;
        bool eq = (u[m] == ustar);
        unsigned bal = __ballot_sync(FULL, eq);
        int pos = base + __popc(bal & ltmask);
        if (eq && pos < KNN) g_idx[(size_t)row * KNN + pos] = m;
        base += __popc(bal);
    }
}

// layers 2-4: distances from precomputed gram rows
__global__ __launch_bounds__(128) void select_gram_kernel() {
    __shared__ uint32_t su[4][NPTS];
    __shared__ uint32_t hist[4][256];
    int warp = threadIdx.x >> 5, lane = threadIdx.x & 31;
    int row = blockIdx.x * 4 + warp;
    int b = row >> 11, n = row & 2047;
    const float* drow = g_gram + (size_t)b * NPTS * NPTS + (size_t)n * NPTS;
    float sqn = g_sq[row];
    uint32_t* u = su[warp];
#pragma unroll 8
    for (int j = 0; j < 64; j++) {
        int m = lane + 32 * j;
        float d = sqn + g_sq[(b << 11) + m] - 2.f * drow[m];
        if (m == n) d = FINF;
        u[m] = fkey(d);
    }
    __syncwarp();
    radix_topk(u, hist[warp], row, lane);
}

// layer 1: distances computed from 3D points on the fly
__global__ __launch_bounds__(128) void select3_kernel(const float* __restrict__ X) {
    __shared__ uint32_t su[4][NPTS];
    __shared__ uint32_t hist[4][256];
    int warp = threadIdx.x >> 5, lane = threadIdx.x & 31;
    int row = blockIdx.x * 4 + warp;
    int b = row >> 11, n = row & 2047;
    const float* Xb = X + (size_t)(b << 11) * 3;
    float xn = Xb[n * 3], yn = Xb[n * 3 + 1], zn = Xb[n * 3 + 2];
    float sqn = g_sq[row];
    uint32_t* u = su[warp];
#pragma unroll 4
    for (int j = 0; j < 64; j++) {
        int m = lane + 32 * j;
        float px = Xb[m * 3], py = Xb[m * 3 + 1], pz = Xb[m * 3 + 2];
        float dot = xn * px + yn * py + zn * pz;
        float d = sqn + g_sq[(b << 11) + m] - 2.f * dot;
        if (m == n) d = FINF;
        u[m] = fkey(d);
    }
    __syncwarp();
    radix_topk(u, hist[warp], row, lane);
}

// ------------------- weight transforms (pre-split bf16) --------------------
__global__ void wtmp_kernel(const float* __restrict__ w, int C, int O) {
    int i = blockIdx.x * 256 + threadIdx.x;
    int tot = C * 2 * O;
    if (i < tot) {
        int c = i / (2 * O);
        int o = i % (2 * O);
        float v;
        if (o < O) v = w[(size_t)o * (2 * C) + c] - w[(size_t)o * (2 * C) + C + c];
        else       v = w[(size_t)(o - O) * (2 * C) + C + c];
        g_wtmp[i] = v;
    }
}

__global__ void wtmp_bf_kernel(const float* __restrict__ w, int C, int O) {
    int i = blockIdx.x * 256 + threadIdx.x;
    int tot = 2 * O * C;
    if (i < tot) {
        int o = i / C;
        int c = i % C;
        float v;
        if (o < O) v = w[(size_t)o * (2 * C) + c] - w[(size_t)o * (2 * C) + C + c];
        else       v = w[(size_t)(o - O) * (2 * C) + C + c];
        __nv_bfloat16 h, l; split_bf16(v, h, l);
        g_wth[i] = h; g_wtl[i] = l;
    }
}

__global__ void wm_conv_kernel(const float* __restrict__ wm) {
    int i = blockIdx.x * 256 + threadIdx.x;   // 1024*512
    float v = wm[i];
    __nv_bfloat16 h, l; split_bf16(v, h, l);
    g_wmh[i] = h; g_wml[i] = l;
}

// ----------------------- layer-1 hh (K=3 feature GEMM) ---------------------
__global__ void hh3_kernel(const float* __restrict__ X) {
    __shared__ float w[3 * 128];
    int row = blockIdx.x;
    int t = threadIdx.x;   // 128
    w[t] = g_wtmp[t]; w[128 + t] = g_wtmp[128 + t]; w[256 + t] = g_wtmp[256 + t];
    __syncthreads();
    float x0 = X[row * 3], x1 = X[row * 3 + 1], x2 = X[row * 3 + 2];
    g_hh[(size_t)row * 128 + t] = x0 * w[t] + x1 * w[128 + t] + x2 * w[256 + t];
}

// ------------------- fused edge gather: stats + hmax/hmin -------------------
__global__ void edge_gather_kernel(int O) {
    __shared__ int   sidx[KNN];
    __shared__ float sacc[8];
    int row = blockIdx.x;
    int b = row >> 11;
    int t = threadIdx.x;     // == c
    if (t < KNN) sidx[t] = g_idx[(size_t)row * KNN + t];
    if (t < 8) sacc[t] = 0.f;
    __syncthreads();
    int twoO = 2 * O;
    float hcv = g_hh[(size_t)row * twoO + t];
    size_t bbase = ((size_t)(b << 11)) * twoO + O + t;
    float s = 0.f, q = 0.f, mx = -FINF, mn = FINF;
#pragma unroll
    for (int k = 0; k < KNN; k++) {
        float h = hcv + g_hh[bbase + (size_t)sidx[k] * twoO];
        s += h; q += h * h;
        mx = fmaxf(mx, h); mn = fminf(mn, h);
    }
    g_hmax[(size_t)row * O + t] = mx;
    g_hmin[(size_t)row * O + t] = mn;
    int gsz = O >> 2;
    int rw = gsz < 32 ? gsz : 32;
#pragma unroll
    for (int off = 16; off > 0; off >>= 1) {
        if (off < rw) {
            s += __shfl_down_sync(0xffffffffu, s, off, 32);
            q += __shfl_down_sync(0xffffffffu, q, off, 32);
        }
    }
    int g = t / gsz;
    if ((t & (rw - 1)) == 0) {
        atomicAdd(&sacc[g * 2 + 0], s);
        atomicAdd(&sacc[g * 2 + 1], q);
    }
    __syncthreads();
    if (t < 8) g_part[(size_t)row * 8 + t] = sacc[t];
}

// ------------------- cross-block stats reduce (edge & seq) ------------------
__global__ __launch_bounds__(256) void stats_reduce_kernel(int perrow, int ngroups,
                                                           float cnt) {
    __shared__ double ds[256], dq[256];
    int g = blockIdx.x, b = blockIdx.y, t = threadIdx.x;
    double s = 0.0, q = 0.0;
    for (int r = t; r < NPTS; r += 256) {
        size_t base = ((size_t)((b << 11) + r)) * perrow + g * 2;
        s += (double)g_part[base];
        q += (double)g_part[base + 1];
    }
    ds[t] = s; dq[t] = q;
    __syncthreads();
    for (int st = 128; st > 0; st >>= 1) {
        if (t < st) { ds[t] += ds[t + st]; dq[t] += dq[t + st]; }
        __syncthreads();
    }
    if (t == 0) {
        double mu = ds[0] / (double)cnt;
        double var = dq[0] / (double)cnt - mu * mu;
        g_mu[b * ngroups + g] = (float)mu;
        g_rs[b * ngroups + g] = rsqrtf((float)var + 1e-5f);
    }
}

// ---- edge final: affine+leaky of hmax/hmin; writes bf16 hi/lo + fused sq ---
__global__ void edge_final_kernel(int O, int coff,
                                  const float* __restrict__ gw,
                                  const float* __restrict__ gb) {
    __shared__ float red[256];
    int row = blockIdx.x;
    int b = row >> 11;
    int t = threadIdx.x;      // == c
    int g = t / (O >> 2);
    float mu = g_mu[b * 4 + g], rs = g_rs[b * 4 + g];
    float a = rs * gw[t];
    float b2 = gb[t] - mu * a;
    float h = (a >= 0.f) ? g_hmax[(size_t)row * O + t] : g_hmin[(size_t)row * O + t];
    float v = leaky02(a * h + b2);
    __nv_bfloat16 vh, vl; split_bf16(v, vh, vl);
    g_ch[(size_t)row * 512 + coff + t] = vh;
    g_cl[(size_t)row * 512 + coff + t] = vl;
    red[t] = v * v;
    __syncthreads();
    for (int st = O >> 1; st > 0; st >>= 1) {
        if (t < st) red[t] += red[t + st];
        __syncthreads();
    }
    if (t == 0) g_sq[row] = red[0];
}

// ------------------------------ seq GN stats --------------------------------
__global__ __launch_bounds__(256) void seq_stats_kernel() {
    __shared__ float sacc[32];
    int row = blockIdx.x;
    int t = threadIdx.x;
    if (t < 32) sacc[t] = 0.f;
    __syncthreads();
    const float* hr = g_hm + (size_t)row * 1024;
    float s = 0.f, q = 0.f;
#pragma unroll
    for (int j = 0; j < 4; j++) { float v = hr[t * 4 + j]; s += v; q += v * v; }
    s += __shfl_down_sync(0xffffffffu, s, 8, 16);
    s += __shfl_down_sync(0xffffffffu, s, 4, 16);
    s += __shfl_down_sync(0xffffffffu, s, 2, 16);
    s += __shfl_down_sync(0xffffffffu, s, 1, 16);
    q += __shfl_down_sync(0xffffffffu, q, 8, 16);
    q += __shfl_down_sync(0xffffffffu, q, 4, 16);
    q += __shfl_down_sync(0xffffffffu, q, 2, 16);
    q += __shfl_down_sync(0xffffffffu, q, 1, 16);
    int g = t >> 4;
    if ((t & 15) == 0) {
        atomicAdd(&sacc[g * 2 + 0], s);
        atomicAdd(&sacc[g * 2 + 1], q);
    }
    __syncthreads();
    if (t < 32) g_part[(size_t)row * 32 + t] = sacc[t];
}

// ------------------- seq normalize + leaky + max over N ---------------------
__global__ __launch_bounds__(256) void seq_max_part(const float* __restrict__ gmw,
                                                    const float* __restrict__ gmb) {
    int c = blockIdx.x * 256 + threadIdx.x;
    int b = blockIdx.y;
    int z = blockIdx.z;
    int g = c >> 6;
    float mu = g_mu[b * 16 + g], rs = g_rs[b * 16 + g];
    float w = gmw[c], bb = gmb[c];
    const float* col = g_hm + ((size_t)b * NPTS + z * 256) * 1024 + c;
    float m = -FINF;
#pragma unroll 4
    for (int n = 0; n < 256; n++) {
        float v = (col[(size_t)n * 1024] - mu) * rs * w + bb;
        m = fmaxf(m, leaky02(v));
    }
    g_pmax[((size_t)b * 8 + z) * 1024 + c] = m;
}

__global__ __launch_bounds__(256) void seq_max_combine() {
    int c = blockIdx.x * 256 + threadIdx.x;
    int b = blockIdx.y;
    float m = -FINF;
#pragma unroll
    for (int z = 0; z < 8; z++)
        m = fmaxf(m, g_pmax[((size_t)b * 8 + z) * 1024 + c]);
    g_gvec[b * 1024 + c] = m;
}

// --------------------------------- MLP head ---------------------------------
__device__ __forceinline__ float bsum256(float v, float* red, int t) {
    red[t] = v; __syncthreads();
    for (int s = 128; s > 0; s >>= 1) {
        if (t < s) red[t] += red[t + s];
        __syncthreads();
    }
    float r = red[0]; __syncthreads();
    return r;
}

__device__ __forceinline__ void ln_leaky(float* buf, int L,
                                         const float* __restrict__ w,
                                         const float* __restrict__ b,
                                         float* red, int t) {
    float s = 0.f, q = 0.f;
    for (int i = t; i < L; i += 256) { float v = buf[i]; s += v; q += v * v; }
    float S = bsum256(s, red, t);
    float Q = bsum256(q, red, t);
    float mu = S / (float)L;
    float var = Q / (float)L - mu * mu;
    float rs = rsqrtf(var + 1e-5f);
    for (int i = t; i < L; i += 256) {
        float v = (buf[i] - mu) * rs * w[i] + b[i];
        buf[i] = leaky02(v);
    }
    __syncthreads();
}

__global__ __launch_bounds__(256) void mlp_kernel(
    const float* __restrict__ fc1w, const float* __restrict__ fc1b,
    const float* __restrict__ ln1w, const float* __restrict__ ln1b,
    const float* __restrict__ fc2w, const float* __restrict__ fc2b,
    const float* __restrict__ ln2w, const float* __restrict__ ln2b,
    const float* __restrict__ fc3w, const float* __restrict__ fc3b,
    const float* __restrict__ ln3w, const float* __restrict__ ln3b,
    const float* __restrict__ fc4w, const float* __restrict__ fc4b,
    float* __restrict__ out)
{
    __shared__ __align__(16) float sin_[1024];
    __shared__ __align__(16) float t1[512];
    __shared__ __align__(16) float t2[256];
    __shared__ __align__(16) float t3[64];
    __shared__ float red[256];
    int b = blockIdx.x, t = threadIdx.x;
    for (int i = t; i < 1024; i += 256) sin_[i] = g_gvec[b * 1024 + i];
    __syncthreads();
    for (int o = t; o < 512; o += 256) {
        float acc = fc1b[o];
        const float4* wr = (const float4*)(fc1w + (size_t)o * 1024);
        const float4* xr = (const float4*)sin_;
        for (int c = 0; c < 256; c++) {
            float4 w4 = wr[c], x4 = xr[c];
            acc += w4.x * x4.x + w4.y * x4.y + w4.z * x4.z + w4.w * x4.w;
        }
        t1[o] = acc;
    }
    __syncthreads();
    ln_leaky(t1, 512, ln1w, ln1b, red, t);
    if (t < 256) {
        float acc = fc2b[t];
        const float4* wr = (const float4*)(fc2w + (size_t)t * 512);
        const float4* xr = (const float4*)t1;
        for (int c = 0; c < 128; c++) {
            float4 w4 = wr[c], x4 = xr[c];
            acc += w4.x * x4.x + w4.y * x4.y + w4.z * x4.z + w4.w * x4.w;
        }
        t2[t] = acc;
    }
    __syncthreads();
    ln_leaky(t2, 256, ln2w, ln2b, red, t);
    if (t < 64) {
        float acc = fc3b[t];
        const float4* wr = (const float4*)(fc3w + (size_t)t * 256);
        const float4* xr = (const float4*)t2;
        for (int c = 0; c < 64; c++) {
            float4 w4 = wr[c], x4 = xr[c];
            acc += w4.x * x4.x + w4.y * x4.y + w4.z * x4.z + w4.w * x4.w;
        }
        t3[t] = acc;
    }
    __syncthreads();
    ln_leaky(t3, 64, ln3w, ln3b, red, t);
    if (t < 2) {
        float acc = fc4b[t];
        for (int c = 0; c < 64; c++) acc += fc4w[t * 64 + c] * t3[c];
        out[b * 2 + t] = acc;
    }
}

// =============================== host driver ================================
extern "C" void kernel_launch(void* const* d_in, const int* in_sizes, int n_in,
                              void* d_out, int out_size)
{
    const float* x    = (const float*)d_in[0];
    const float* w1   = (const float*)d_in[1];
    const float* g1w  = (const float*)d_in[2];
    const float* g1b  = (const float*)d_in[3];
    const float* w2   = (const float*)d_in[4];
    const float* g2w  = (const float*)d_in[5];
    const float* g2b  = (const float*)d_in[6];
    const float* w3   = (const float*)d_in[7];
    const float* g3w  = (const float*)d_in[8];
    const float* g3b  = (const float*)d_in[9];
    const float* w4   = (const float*)d_in[10];
    const float* g4w  = (const float*)d_in[11];
    const float* g4b  = (const float*)d_in[12];
    const float* wm   = (const float*)d_in[13];
    const float* gmw  = (const float*)d_in[14];
    const float* gmb  = (const float*)d_in[15];
    const float* fc1w = (const float*)d_in[16];
    const float* fc1b = (const float*)d_in[17];
    const float* ln1w = (const float*)d_in[18];
    const float* ln1b = (const float*)d_in[19];
    const float* fc2w = (const float*)d_in[20];
    const float* fc2b = (const float*)d_in[21];
    const float* ln2w = (const float*)d_in[22];
    const float* ln2b = (const float*)d_in[23];
    const float* fc3w = (const float*)d_in[24];
    const float* fc3b = (const float*)d_in[25];
    const float* ln3w = (const float*)d_in[26];
    const float* ln3b = (const float*)d_in[27];
    const float* fc4w = (const float*)d_in[28];
    const float* fc4b = (const float*)d_in[29];
    float* out = (float*)d_out;

    float *pGram, *pHH, *pHm;
    __nv_bfloat16 *pCh, *pCl, *pWth, *pWtl, *pWmh, *pWml;
    cudaGetSymbolAddress((void**)&pGram, g_gram);
    cudaGetSymbolAddress((void**)&pHH,   g_hh);
    cudaGetSymbolAddress((void**)&pHm,   g_hm);
    cudaGetSymbolAddress((void**)&pCh,   g_ch);
    cudaGetSymbolAddress((void**)&pCl,   g_cl);
    cudaGetSymbolAddress((void**)&pWth,  g_wth);
    cudaGetSymbolAddress((void**)&pWtl,  g_wtl);
    cudaGetSymbolAddress((void**)&pWmh,  g_wmh);
    cudaGetSymbolAddress((void**)&pWml,  g_wml);

    cudaFuncSetAttribute(mmagemm_bf<true>,
                         cudaFuncAttributeMaxDynamicSharedMemorySize, GEMM_SMEM);
    cudaFuncSetAttribute(mmagemm_bf<false>,
                         cudaFuncAttributeMaxDynamicSharedMemorySize, GEMM_SMEM);

    // weight prep (independent of pipeline; run first)
    wm_conv_kernel<<<(1024 * 512) / 256, 256>>>(wm);

    // ---------------- layer 1 (C=3, O=64) ----------------------------------
    sq_kernel<<<(NROWS + 255) / 256, 256>>>(x);
    wtmp_kernel<<<(3 * 128 + 255) / 256, 256>>>(w1, 3, 64);
    hh3_kernel<<<NROWS, 128>>>(x);
    select3_kernel<<<NROWS / 4, 128>>>(x);
    edge_gather_kernel<<<NROWS, 64>>>(64);
    stats_reduce_kernel<<<dim3(4, NB), 256>>>(8, 4, (float)(NPTS * KNN * 16));
    edge_final_kernel<<<NROWS, 64>>>(64, 0, g1w, g1b);

    // ---------------- layers 2-4 ------------------------------------------
    struct LayerCfg {
        int coffin;   // input slice offset in g_ch/g_cl
        int C; int O;
        const float* w; const float* gw; const float* gb; int coff;
    };
    LayerCfg layers[3] = {
        { 0,   64,  64,  w2, g2w, g2b, 64  },
        { 64,  64,  128, w3, g3w, g3b, 128 },
        { 128, 128, 256, w4, g4w, g4b, 256 },
    };

    const int NTILES = (NPTS / 128) * (NPTS / 128 + 1) / 2;   // 136

    for (int l = 0; l < 3; l++) {
        const LayerCfg& L = layers[l];
        mmagemm_bf<true><<<dim3(NTILES, 1, NB), 256, GEMM_SMEM>>>(
            pCh + L.coffin, pCl + L.coffin, 512, (size_t)NPTS * 512,
            pCh + L.coffin, pCl + L.coffin, 512, (size_t)NPTS * 512,
            pGram, NPTS, (size_t)NPTS * NPTS, L.C);
        select_gram_kernel<<<NROWS / 4, 128>>>();
        wtmp_bf_kernel<<<(2 * L.O * L.C + 255) / 256, 256>>>(L.w, L.C, L.O);
        mmagemm_bf<false><<<dim3(2 * L.O / 128, NROWS / 128, 1), 256, GEMM_SMEM>>>(
            pCh + L.coffin, pCl + L.coffin, 512, 0,
            pWth, pWtl, L.C, 0,
            pHH, 2 * L.O, 0, L.C);
        edge_gather_kernel<<<NROWS, L.O>>>(L.O);
        stats_reduce_kernel<<<dim3(4, NB), 256>>>(8, 4, (float)(NPTS * KNN * (L.O / 4)));
        edge_final_kernel<<<NROWS, L.O>>>(L.O, L.coff, L.gw, L.gb);
    }

    // mid: hm = concat @ wm^T  (16384 x 512 -> 1024)
    mmagemm_bf<false><<<dim3(1024 / 128, NROWS / 128, 1), 256, GEMM_SMEM>>>(
        pCh, pCl, 512, 0, pWmh, pWml, 512, 0, pHm, 1024, 0, 512);
    seq_stats_kernel<<<NROWS, 256>>>();
    stats_reduce_kernel<<<dim3(16, NB), 256>>>(32, 16, (float)(NPTS * 64));
    seq_max_part<<<dim3(4, NB, 8), 256>>>(gmw, gmb);
    seq_max_combine<<<dim3(4, NB), 256>>>();

    // head MLP
    mlp_kernel<<<NB, 256>>>(fc1w, fc1b, ln1w, ln1b,
                            fc2w, fc2b, ln2w, ln2b,
                            fc3w, fc3b, ln3w, ln3b,
                            fc4w, fc4b, out);
}

// round 11
// speedup vs baseline: 1.2754x; 1.2754x over previous
#include <cuda_runtime.h>
#include <cuda_bf16.h>
#include <cstdint>
#include <cstddef>

// ---------------------------------------------------------------------------
// DGCNN pipeline. B=8, N=2048, K=20.
// Round 11: round 9 baseline (radix select REVERTED) + redux.sync argmin in
// the iterative top-20 select (2 redux ops replace each 5-step shfl butterfly,
// exact same selection semantics incl. lowest-index tie-break).
// ---------------------------------------------------------------------------

#define NPTS   2048
#define NB     8
#define NROWS  (NB*NPTS)   // 16384
#define KNN    20
#define FINF   3.4e38f

// ------------------------- device scratch (no allocs) ----------------------
__device__ float  g_gram[(size_t)NB * NPTS * NPTS];   // reused per layer
__device__ float  g_hh[(size_t)NROWS * 512];          // [rows x 2O], hc | hn
__device__ float  g_hm[(size_t)NROWS * 1024];         // seq features
__device__ float  g_hmax[(size_t)NROWS * 256];
__device__ float  g_hmin[(size_t)NROWS * 256];
__device__ float  g_sq[NROWS];
__device__ int    g_idx[(size_t)NROWS * KNN];
__device__ float  g_wtmp[3 * 128];                    // layer-1 fp32 weights
__device__ float  g_part[(size_t)NROWS * 32];         // per-row group partials
__device__ float  g_mu[128];
__device__ float  g_rs[128];
__device__ float  g_pmax[NB * 8 * 1024];              // seq max partials
__device__ float  g_gvec[NB * 1024];
// bf16 split operands
__device__ __align__(16) __nv_bfloat16 g_ch[(size_t)NROWS * 512];   // concat hi
__device__ __align__(16) __nv_bfloat16 g_cl[(size_t)NROWS * 512];   // concat lo
__device__ __align__(16) __nv_bfloat16 g_wth[512 * 128];            // wtmp^T hi [2O][C]
__device__ __align__(16) __nv_bfloat16 g_wtl[512 * 128];            // wtmp^T lo
__device__ __align__(16) __nv_bfloat16 g_wmh[1024 * 512];           // wm hi
__device__ __align__(16) __nv_bfloat16 g_wml[1024 * 512];           // wm lo

__device__ __forceinline__ float leaky02(float v) { return v > 0.f ? v : 0.2f * v; }
__device__ __forceinline__ int   skew(int m)      { return m + (m >> 5); }
#define SD_LEN 2112

__device__ __forceinline__ void split_bf16(float v, __nv_bfloat16& h, __nv_bfloat16& l) {
    h = __float2bfloat16(v);
    l = __float2bfloat16(v - __bfloat162float(h));
}

// --------------------------- cp.async helpers -------------------------------
__device__ __forceinline__ void cp16(void* smem, const void* g) {
    uint32_t s = (uint32_t)__cvta_generic_to_shared(smem);
    asm volatile("cp.async.cg.shared.global [%0], [%1], 16;" :: "r"(s), "l"(g));
}
__device__ __forceinline__ void cp_commit() {
    asm volatile("cp.async.commit_group;");
}
template <int N>
__device__ __forceinline__ void cp_wait() {
    asm volatile("cp.async.wait_group %0;" :: "n"(N));
}

// ------------------------------ sq kernel (layer 1 only) -------------------
__global__ void sq_kernel(const float* __restrict__ X) {
    int r = blockIdx.x * 256 + threadIdx.x;
    if (r < NROWS) {
        float a = X[r * 3], b = X[r * 3 + 1], c = X[r * 3 + 2];
        g_sq[r] = a * a + b * b + c * c;
    }
}

// ================= tensor-core GEMM: pre-split bf16, fp32 accum =============
__device__ __forceinline__ void mma16816(float c[4], const uint32_t a[4],
                                         const uint32_t b[2]) {
    asm volatile(
        "mma.sync.aligned.m16n8k16.row.col.f32.bf16.bf16.f32 "
        "{%0,%1,%2,%3}, {%4,%5,%6,%7}, {%8,%9}, {%0,%1,%2,%3};\n"
        : "+f"(c[0]), "+f"(c[1]), "+f"(c[2]), "+f"(c[3])
        : "r"(a[0]), "r"(a[1]), "r"(a[2]), "r"(a[3]), "r"(b[0]), "r"(b[1]));
}

#define SMS 40                 // smem k-stride in u16 (32 + 8 pad, conflict-free)
#define STAGE_U16 (4 * 128 * SMS)   // Ah|Al|Bh|Bl per stage
#define GEMM_SMEM (2 * STAGE_U16 * 2)  // bytes: 81920

template <bool SYM>
__global__ __launch_bounds__(256, 2) void mmagemm_bf(
    const __nv_bfloat16* __restrict__ pAh, const __nv_bfloat16* __restrict__ pAl,
    int lda, size_t sA,
    const __nv_bfloat16* __restrict__ pBh, const __nv_bfloat16* __restrict__ pBl,
    int ldb, size_t sB,
    float* __restrict__ Cp, int ldc, size_t sC, int K)
{
    extern __shared__ __align__(16) uint16_t dyn[];
    const __nv_bfloat16* Abh = pAh + (size_t)blockIdx.z * sA;
    const __nv_bfloat16* Abl = pAl + (size_t)blockIdx.z * sA;
    const __nv_bfloat16* Bbh = pBh + (size_t)blockIdx.z * sB;
    const __nv_bfloat16* Bbl = pBl + (size_t)blockIdx.z * sB;
    float* Cb = Cp + (size_t)blockIdx.z * sC;

    int m0, n0;
    if (SYM) {
        int i = blockIdx.x;
        int bx = (int)((sqrtf(8.f * (float)i + 1.f) - 1.f) * 0.5f);
        while ((bx + 1) * (bx + 2) / 2 <= i) bx++;
        while (bx * (bx + 1) / 2 > i) bx--;
        int by = i - bx * (bx + 1) / 2;
        m0 = by * 128; n0 = bx * 128;
    } else {
        m0 = blockIdx.y * 128; n0 = blockIdx.x * 128;
    }

    const int tid = threadIdx.x;
    const int warp = tid >> 5, lane = tid & 31;
    const int wrm = warp >> 1, wrn = warp & 1;
    const int g = lane >> 2, q = lane & 3;
    const int row = tid >> 1, c0 = (tid & 1) * 16;

    float acc[2][8][4];
#pragma unroll
    for (int mt = 0; mt < 2; mt++)
#pragma unroll
        for (int nt = 0; nt < 8; nt++)
#pragma unroll
            for (int j = 0; j < 4; j++) acc[mt][nt][j] = 0.f;

    const int nk = K >> 5;

    auto load_stage = [&](int st, int k0) {
        uint16_t* S  = dyn + st * STAGE_U16;
        uint16_t* Ah = S;
        uint16_t* Al = S + 128 * SMS;
        uint16_t* Bh = S + 2 * 128 * SMS;
        uint16_t* Bl = S + 3 * 128 * SMS;
        const size_t aoff = (size_t)(m0 + row) * lda + k0 + c0;
        const size_t boff = (size_t)(n0 + row) * ldb + k0 + c0;
        cp16(&Ah[row * SMS + c0],     &Abh[aoff]);
        cp16(&Ah[row * SMS + c0 + 8], &Abh[aoff + 8]);
        cp16(&Al[row * SMS + c0],     &Abl[aoff]);
        cp16(&Al[row * SMS + c0 + 8], &Abl[aoff + 8]);
        cp16(&Bh[row * SMS + c0],     &Bbh[boff]);
        cp16(&Bh[row * SMS + c0 + 8], &Bbh[boff + 8]);
        cp16(&Bl[row * SMS + c0],     &Bbl[boff]);
        cp16(&Bl[row * SMS + c0 + 8], &Bbl[boff + 8]);
        cp_commit();
    };

    load_stage(0, 0);

    for (int kc = 0; kc < nk; kc++) {
        if (kc + 1 < nk) {
            load_stage((kc + 1) & 1, (kc + 1) << 5);
            cp_wait<1>();
        } else {
            cp_wait<0>();
        }
        __syncthreads();

        uint16_t* S  = dyn + (kc & 1) * STAGE_U16;
        uint16_t* Ah = S;
        uint16_t* Al = S + 128 * SMS;
        uint16_t* Bh = S + 2 * 128 * SMS;
        uint16_t* Bl = S + 3 * 128 * SMS;

#pragma unroll
        for (int ks = 0; ks < 32; ks += 16) {
            const int cb = ks + q * 2;
            uint32_t afh[2][4], afl[2][4];
#pragma unroll
            for (int mt = 0; mt < 2; mt++) {
                int r = wrm * 32 + mt * 16 + g;
                afh[mt][0] = *(const uint32_t*)&Ah[r * SMS + cb];
                afh[mt][1] = *(const uint32_t*)&Ah[(r + 8) * SMS + cb];
                afh[mt][2] = *(const uint32_t*)&Ah[r * SMS + cb + 8];
                afh[mt][3] = *(const uint32_t*)&Ah[(r + 8) * SMS + cb + 8];
                afl[mt][0] = *(const uint32_t*)&Al[r * SMS + cb];
                afl[mt][1] = *(const uint32_t*)&Al[(r + 8) * SMS + cb];
                afl[mt][2] = *(const uint32_t*)&Al[r * SMS + cb + 8];
                afl[mt][3] = *(const uint32_t*)&Al[(r + 8) * SMS + cb + 8];
            }
#pragma unroll
            for (int nt = 0; nt < 8; nt++) {
                int n = wrn * 64 + nt * 8 + g;
                uint32_t bfh[2], bfl[2];
                bfh[0] = *(const uint32_t*)&Bh[n * SMS + cb];
                bfh[1] = *(const uint32_t*)&Bh[n * SMS + cb + 8];
                bfl[0] = *(const uint32_t*)&Bl[n * SMS + cb];
                bfl[1] = *(const uint32_t*)&Bl[n * SMS + cb + 8];
#pragma unroll
                for (int mt = 0; mt < 2; mt++) {
                    mma16816(acc[mt][nt], afh[mt], bfh);
                    mma16816(acc[mt][nt], afh[mt], bfl);
                    mma16816(acc[mt][nt], afl[mt], bfh);
                }
            }
        }
        __syncthreads();
    }

#pragma unroll
    for (int mt = 0; mt < 2; mt++) {
        int r0 = m0 + wrm * 32 + mt * 16 + g;
#pragma unroll
        for (int nt = 0; nt < 8; nt++) {
            int cc = n0 + wrn * 64 + nt * 8 + q * 2;
            *(float2*)&Cb[(size_t)r0 * ldc + cc] =
                make_float2(acc[mt][nt][0], acc[mt][nt][1]);
            *(float2*)&Cb[(size_t)(r0 + 8) * ldc + cc] =
                make_float2(acc[mt][nt][2], acc[mt][nt][3]);
            if (SYM && n0 != m0) {
                Cb[(size_t)cc * ldc + r0]           = acc[mt][nt][0];
                Cb[(size_t)(cc + 1) * ldc + r0]     = acc[mt][nt][1];
                Cb[(size_t)cc * ldc + r0 + 8]       = acc[mt][nt][2];
                Cb[(size_t)(cc + 1) * ldc + r0 + 8] = acc[mt][nt][3];
            }
        }
    }
}

// ============ warp-per-query top-20: redux.sync argmin, skewed smem =========
// Keys: order-preserving uint map of fp32 distance (lower distance = lower
// key). Exact argmin with lowest-index tie-break via two __reduce_min_sync.
__device__ __forceinline__ uint32_t fkey(float d) {
    uint32_t b = __float_as_uint(d);
    return (b & 0x80000000u) ? ~b : (b | 0x80000000u);
}

__device__ __forceinline__ void topk_from_smem(uint32_t* sd, int row, int lane,
                                               uint32_t bv, int bi) {
    const unsigned FULL = 0xffffffffu;
#pragma unroll 1
    for (int it = 0; it < KNN; it++) {
        // global min key, then lowest index among equal keys
        uint32_t gmin = __reduce_min_sync(FULL, bv);
        uint32_t cand = (bv == gmin) ? (uint32_t)bi : 0xffffffffu;
        uint32_t gidx = __reduce_min_sync(FULL, cand);
        if (lane == 0) {
            g_idx[(size_t)row * KNN + it] = (int)gidx;
            sd[skew((int)gidx)] = 0xffffffffu;
        }
        __syncwarp();
        // cooperative rescan of winner lane's column (conflict-free via skew)
        int wl = (int)gidx & 31;
        int m0 = wl + 32 * (2 * lane);
        int m1 = m0 + 32;
        uint32_t d0 = sd[skew(m0)];
        uint32_t d1 = sd[skew(m1)];
        uint32_t rv = d0 < d1 ? d0 : d1;            // tie -> lower m (m0)
        int      rb = d0 <= d1 ? m0 : m1;
        uint32_t rmin = __reduce_min_sync(FULL, rv);
        uint32_t cnd2 = (rv == rmin) ? (uint32_t)rb : 0xffffffffu;
        uint32_t ridx = __reduce_min_sync(FULL, cnd2);
        if (lane == wl) { bv = rmin; bi = (int)ridx; }
    }
}

// layers 2-4: distances from precomputed gram rows
__global__ __launch_bounds__(128) void select_gram_kernel() {
    __shared__ uint32_t sd[4][SD_LEN];
    int warp = threadIdx.x >> 5, lane = threadIdx.x & 31;
    int row = blockIdx.x * 4 + warp;
    int b = row >> 11, n = row & 2047;
    const float* drow = g_gram + (size_t)b * NPTS * NPTS + (size_t)n * NPTS;
    float sqn = g_sq[row];
    uint32_t* sdw = sd[warp];
    uint32_t bv = 0xffffffffu; int bi = 0x7fffffff;
#pragma unroll 8
    for (int j = 0; j < 64; j++) {
        int m = lane + 32 * j;
        float d = sqn + g_sq[(b << 11) + m] - 2.f * drow[m];
        uint32_t k = (m == n) ? 0xffffffffu : fkey(d);
        sdw[skew(m)] = k;
        if (k < bv) { bv = k; bi = m; }   // j ascending -> ties keep lowest m
    }
    __syncwarp();
    topk_from_smem(sdw, row, lane, bv, bi);
}

// layer 1: distances computed from 3D points on the fly
__global__ __launch_bounds__(128) void select3_kernel(const float* __restrict__ X) {
    __shared__ uint32_t sd[4][SD_LEN];
    int warp = threadIdx.x >> 5, lane = threadIdx.x & 31;
    int row = blockIdx.x * 4 + warp;
    int b = row >> 11, n = row & 2047;
    const float* Xb = X + (size_t)(b << 11) * 3;
    float xn = Xb[n * 3], yn = Xb[n * 3 + 1], zn = Xb[n * 3 + 2];
    float sqn = g_sq[row];
    uint32_t* sdw = sd[warp];
    uint32_t bv = 0xffffffffu; int bi = 0x7fffffff;
#pragma unroll 4
    for (int j = 0; j < 64; j++) {
        int m = lane + 32 * j;
        float px = Xb[m * 3], py = Xb[m * 3 + 1], pz = Xb[m * 3 + 2];
        float dot = xn * px + yn * py + zn * pz;
        float d = sqn + g_sq[(b << 11) + m] - 2.f * dot;
        uint32_t k = (m == n) ? 0xffffffffu : fkey(d);
        sdw[skew(m)] = k;
        if (k < bv) { bv = k; bi = m; }
    }
    __syncwarp();
    topk_from_smem(sdw, row, lane, bv, bi);
}

// ------------------- weight transforms (pre-split bf16) --------------------
__global__ void wtmp_kernel(const float* __restrict__ w, int C, int O) {
    int i = blockIdx.x * 256 + threadIdx.x;
    int tot = C * 2 * O;
    if (i < tot) {
        int c = i / (2 * O);
        int o = i % (2 * O);
        float v;
        if (o < O) v = w[(size_t)o * (2 * C) + c] - w[(size_t)o * (2 * C) + C + c];
        else       v = w[(size_t)(o - O) * (2 * C) + C + c];
        g_wtmp[i] = v;
    }
}

__global__ void wtmp_bf_kernel(const float* __restrict__ w, int C, int O) {
    int i = blockIdx.x * 256 + threadIdx.x;
    int tot = 2 * O * C;
    if (i < tot) {
        int o = i / C;
        int c = i % C;
        float v;
        if (o < O) v = w[(size_t)o * (2 * C) + c] - w[(size_t)o * (2 * C) + C + c];
        else       v = w[(size_t)(o - O) * (2 * C) + C + c];
        __nv_bfloat16 h, l; split_bf16(v, h, l);
        g_wth[i] = h; g_wtl[i] = l;
    }
}

__global__ void wm_conv_kernel(const float* __restrict__ wm) {
    int i = blockIdx.x * 256 + threadIdx.x;   // 1024*512
    float v = wm[i];
    __nv_bfloat16 h, l; split_bf16(v, h, l);
    g_wmh[i] = h; g_wml[i] = l;
}

// ----------------------- layer-1 hh (K=3 feature GEMM) ---------------------
__global__ void hh3_kernel(const float* __restrict__ X) {
    __shared__ float w[3 * 128];
    int row = blockIdx.x;
    int t = threadIdx.x;   // 128
    w[t] = g_wtmp[t]; w[128 + t] = g_wtmp[128 + t]; w[256 + t] = g_wtmp[256 + t];
    __syncthreads();
    float x0 = X[row * 3], x1 = X[row * 3 + 1], x2 = X[row * 3 + 2];
    g_hh[(size_t)row * 128 + t] = x0 * w[t] + x1 * w[128 + t] + x2 * w[256 + t];
}

// ------------------- fused edge gather: stats + hmax/hmin -------------------
__global__ void edge_gather_kernel(int O) {
    __shared__ int   sidx[KNN];
    __shared__ float sacc[8];
    int row = blockIdx.x;
    int b = row >> 11;
    int t = threadIdx.x;     // == c
    if (t < KNN) sidx[t] = g_idx[(size_t)row * KNN + t];
    if (t < 8) sacc[t] = 0.f;
    __syncthreads();
    int twoO = 2 * O;
    float hcv = g_hh[(size_t)row * twoO + t];
    size_t bbase = ((size_t)(b << 11)) * twoO + O + t;
    float s = 0.f, q = 0.f, mx = -FINF, mn = FINF;
#pragma unroll
    for (int k = 0; k < KNN; k++) {
        float h = hcv + g_hh[bbase + (size_t)sidx[k] * twoO];
        s += h; q += h * h;
        mx = fmaxf(mx, h); mn = fminf(mn, h);
    }
    g_hmax[(size_t)row * O + t] = mx;
    g_hmin[(size_t)row * O + t] = mn;
    int gsz = O >> 2;
    int rw = gsz < 32 ? gsz : 32;
#pragma unroll
    for (int off = 16; off > 0; off >>= 1) {
        if (off < rw) {
            s += __shfl_down_sync(0xffffffffu, s, off, 32);
            q += __shfl_down_sync(0xffffffffu, q, off, 32);
        }
    }
    int g = t / gsz;
    if ((t & (rw - 1)) == 0) {
        atomicAdd(&sacc[g * 2 + 0], s);
        atomicAdd(&sacc[g * 2 + 1], q);
    }
    __syncthreads();
    if (t < 8) g_part[(size_t)row * 8 + t] = sacc[t];
}

// ------------------- cross-block stats reduce (edge & seq) ------------------
__global__ __launch_bounds__(256) void stats_reduce_kernel(int perrow, int ngroups,
                                                           float cnt) {
    __shared__ double ds[256], dq[256];
    int g = blockIdx.x, b = blockIdx.y, t = threadIdx.x;
    double s = 0.0, q = 0.0;
    for (int r = t; r < NPTS; r += 256) {
        size_t base = ((size_t)((b << 11) + r)) * perrow + g * 2;
        s += (double)g_part[base];
        q += (double)g_part[base + 1];
    }
    ds[t] = s; dq[t] = q;
    __syncthreads();
    for (int st = 128; st > 0; st >>= 1) {
        if (t < st) { ds[t] += ds[t + st]; dq[t] += dq[t + st]; }
        __syncthreads();
    }
    if (t == 0) {
        double mu = ds[0] / (double)cnt;
        double var = dq[0] / (double)cnt - mu * mu;
        g_mu[b * ngroups + g] = (float)mu;
        g_rs[b * ngroups + g] = rsqrtf((float)var + 1e-5f);
    }
}

// ---- edge final: affine+leaky of hmax/hmin; writes bf16 hi/lo + fused sq ---
__global__ void edge_final_kernel(int O, int coff,
                                  const float* __restrict__ gw,
                                  const float* __restrict__ gb) {
    __shared__ float red[256];
    int row = blockIdx.x;
    int b = row >> 11;
    int t = threadIdx.x;      // == c
    int g = t / (O >> 2);
    float mu = g_mu[b * 4 + g], rs = g_rs[b * 4 + g];
    float a = rs * gw[t];
    float b2 = gb[t] - mu * a;
    float h = (a >= 0.f) ? g_hmax[(size_t)row * O + t] : g_hmin[(size_t)row * O + t];
    float v = leaky02(a * h + b2);
    __nv_bfloat16 vh, vl; split_bf16(v, vh, vl);
    g_ch[(size_t)row * 512 + coff + t] = vh;
    g_cl[(size_t)row * 512 + coff + t] = vl;
    red[t] = v * v;
    __syncthreads();
    for (int st = O >> 1; st > 0; st >>= 1) {
        if (t < st) red[t] += red[t + st];
        __syncthreads();
    }
    if (t == 0) g_sq[row] = red[0];
}

// ------------------------------ seq GN stats --------------------------------
__global__ __launch_bounds__(256) void seq_stats_kernel() {
    __shared__ float sacc[32];
    int row = blockIdx.x;
    int t = threadIdx.x;
    if (t < 32) sacc[t] = 0.f;
    __syncthreads();
    const float* hr = g_hm + (size_t)row * 1024;
    float s = 0.f, q = 0.f;
#pragma unroll
    for (int j = 0; j < 4; j++) { float v = hr[t * 4 + j]; s += v; q += v * v; }
    s += __shfl_down_sync(0xffffffffu, s, 8, 16);
    s += __shfl_down_sync(0xffffffffu, s, 4, 16);
    s += __shfl_down_sync(0xffffffffu, s, 2, 16);
    s += __shfl_down_sync(0xffffffffu, s, 1, 16);
    q += __shfl_down_sync(0xffffffffu, q, 8, 16);
    q += __shfl_down_sync(0xffffffffu, q, 4, 16);
    q += __shfl_down_sync(0xffffffffu, q, 2, 16);
    q += __shfl_down_sync(0xffffffffu, q, 1, 16);
    int g = t >> 4;
    if ((t & 15) == 0) {
        atomicAdd(&sacc[g * 2 + 0], s);
        atomicAdd(&sacc[g * 2 + 1], q);
    }
    __syncthreads();
    if (t < 32) g_part[(size_t)row * 32 + t] = sacc[t];
}

// ------------------- seq normalize + leaky + max over N ---------------------
__global__ __launch_bounds__(256) void seq_max_part(const float* __restrict__ gmw,
                                                    const float* __restrict__ gmb) {
    int c = blockIdx.x * 256 + threadIdx.x;
    int b = blockIdx.y;
    int z = blockIdx.z;
    int g = c >> 6;
    float mu = g_mu[b * 16 + g], rs = g_rs[b * 16 + g];
    float w = gmw[c], bb = gmb[c];
    const float* col = g_hm + ((size_t)b * NPTS + z * 256) * 1024 + c;
    float m = -FINF;
#pragma unroll 4
    for (int n = 0; n < 256; n++) {
        float v = (col[(size_t)n * 1024] - mu) * rs * w + bb;
        m = fmaxf(m, leaky02(v));
    }
    g_pmax[((size_t)b * 8 + z) * 1024 + c] = m;
}

__global__ __launch_bounds__(256) void seq_max_combine() {
    int c = blockIdx.x * 256 + threadIdx.x;
    int b = blockIdx.y;
    float m = -FINF;
#pragma unroll
    for (int z = 0; z < 8; z++)
        m = fmaxf(m, g_pmax[((size_t)b * 8 + z) * 1024 + c]);
    g_gvec[b * 1024 + c] = m;
}

// --------------------------------- MLP head ---------------------------------
__device__ __forceinline__ float bsum256(float v, float* red, int t) {
    red[t] = v; __syncthreads();
    for (int s = 128; s > 0; s >>= 1) {
        if (t < s) red[t] += red[t + s];
        __syncthreads();
    }
    float r = red[0]; __syncthreads();
    return r;
}

__device__ __forceinline__ void ln_leaky(float* buf, int L,
                                         const float* __restrict__ w,
                                         const float* __restrict__ b,
                                         float* red, int t) {
    float s = 0.f, q = 0.f;
    for (int i = t; i < L; i += 256) { float v = buf[i]; s += v; q += v * v; }
    float S = bsum256(s, red, t);
    float Q = bsum256(q, red, t);
    float mu = S / (float)L;
    float var = Q / (float)L - mu * mu;
    float rs = rsqrtf(var + 1e-5f);
    for (int i = t; i < L; i += 256) {
        float v = (buf[i] - mu) * rs * w[i] + b[i];
        buf[i] = leaky02(v);
    }
    __syncthreads();
}

__global__ __launch_bounds__(256) void mlp_kernel(
    const float* __restrict__ fc1w, const float* __restrict__ fc1b,
    const float* __restrict__ ln1w, const float* __restrict__ ln1b,
    const float* __restrict__ fc2w, const float* __restrict__ fc2b,
    const float* __restrict__ ln2w, const float* __restrict__ ln2b,
    const float* __restrict__ fc3w, const float* __restrict__ fc3b,
    const float* __restrict__ ln3w, const float* __restrict__ ln3b,
    const float* __restrict__ fc4w, const float* __restrict__ fc4b,
    float* __restrict__ out)
{
    __shared__ __align__(16) float sin_[1024];
    __shared__ __align__(16) float t1[512];
    __shared__ __align__(16) float t2[256];
    __shared__ __align__(16) float t3[64];
    __shared__ float red[256];
    int b = blockIdx.x, t = threadIdx.x;
    for (int i = t; i < 1024; i += 256) sin_[i] = g_gvec[b * 1024 + i];
    __syncthreads();
    for (int o = t; o < 512; o += 256) {
        float acc = fc1b[o];
        const float4* wr = (const float4*)(fc1w + (size_t)o * 1024);
        const float4* xr = (const float4*)sin_;
        for (int c = 0; c < 256; c++) {
            float4 w4 = wr[c], x4 = xr[c];
            acc += w4.x * x4.x + w4.y * x4.y + w4.z * x4.z + w4.w * x4.w;
        }
        t1[o] = acc;
    }
    __syncthreads();
    ln_leaky(t1, 512, ln1w, ln1b, red, t);
    if (t < 256) {
        float acc = fc2b[t];
        const float4* wr = (const float4*)(fc2w + (size_t)t * 512);
        const float4* xr = (const float4*)t1;
        for (int c = 0; c < 128; c++) {
            float4 w4 = wr[c], x4 = xr[c];
            acc += w4.x * x4.x + w4.y * x4.y + w4.z * x4.z + w4.w * x4.w;
        }
        t2[t] = acc;
    }
    __syncthreads();
    ln_leaky(t2, 256, ln2w, ln2b, red, t);
    if (t < 64) {
        float acc = fc3b[t];
        const float4* wr = (const float4*)(fc3w + (size_t)t * 256);
        const float4* xr = (const float4*)t2;
        for (int c = 0; c < 64; c++) {
            float4 w4 = wr[c], x4 = xr[c];
            acc += w4.x * x4.x + w4.y * x4.y + w4.z * x4.z + w4.w * x4.w;
        }
        t3[t] = acc;
    }
    __syncthreads();
    ln_leaky(t3, 64, ln3w, ln3b, red, t);
    if (t < 2) {
        float acc = fc4b[t];
        for (int c = 0; c < 64; c++) acc += fc4w[t * 64 + c] * t3[c];
        out[b * 2 + t] = acc;
    }
}

// =============================== host driver ================================
extern "C" void kernel_launch(void* const* d_in, const int* in_sizes, int n_in,
                              void* d_out, int out_size)
{
    const float* x    = (const float*)d_in[0];
    const float* w1   = (const float*)d_in[1];
    const float* g1w  = (const float*)d_in[2];
    const float* g1b  = (const float*)d_in[3];
    const float* w2   = (const float*)d_in[4];
    const float* g2w  = (const float*)d_in[5];
    const float* g2b  = (const float*)d_in[6];
    const float* w3   = (const float*)d_in[7];
    const float* g3w  = (const float*)d_in[8];
    const float* g3b  = (const float*)d_in[9];
    const float* w4   = (const float*)d_in[10];
    const float* g4w  = (const float*)d_in[11];
    const float* g4b  = (const float*)d_in[12];
    const float* wm   = (const float*)d_in[13];
    const float* gmw  = (const float*)d_in[14];
    const float* gmb  = (const float*)d_in[15];
    const float* fc1w = (const float*)d_in[16];
    const float* fc1b = (const float*)d_in[17];
    const float* ln1w = (const float*)d_in[18];
    const float* ln1b = (const float*)d_in[19];
    const float* fc2w = (const float*)d_in[20];
    const float* fc2b = (const float*)d_in[21];
    const float* ln2w = (const float*)d_in[22];
    const float* ln2b = (const float*)d_in[23];
    const float* fc3w = (const float*)d_in[24];
    const float* fc3b = (const float*)d_in[25];
    const float* ln3w = (const float*)d_in[26];
    const float* ln3b = (const float*)d_in[27];
    const float* fc4w = (const float*)d_in[28];
    const float* fc4b = (const float*)d_in[29];
    float* out = (float*)d_out;

    float *pGram, *pHH, *pHm;
    __nv_bfloat16 *pCh, *pCl, *pWth, *pWtl, *pWmh, *pWml;
    cudaGetSymbolAddress((void**)&pGram, g_gram);
    cudaGetSymbolAddress((void**)&pHH,   g_hh);
    cudaGetSymbolAddress((void**)&pHm,   g_hm);
    cudaGetSymbolAddress((void**)&pCh,   g_ch);
    cudaGetSymbolAddress((void**)&pCl,   g_cl);
    cudaGetSymbolAddress((void**)&pWth,  g_wth);
    cudaGetSymbolAddress((void**)&pWtl,  g_wtl);
    cudaGetSymbolAddress((void**)&pWmh,  g_wmh);
    cudaGetSymbolAddress((void**)&pWml,  g_wml);

    cudaFuncSetAttribute(mmagemm_bf<true>,
                         cudaFuncAttributeMaxDynamicSharedMemorySize, GEMM_SMEM);
    cudaFuncSetAttribute(mmagemm_bf<false>,
                         cudaFuncAttributeMaxDynamicSharedMemorySize, GEMM_SMEM);

    // weight prep (independent of pipeline; run first)
    wm_conv_kernel<<<(1024 * 512) / 256, 256>>>(wm);

    // ---------------- layer 1 (C=3, O=64) ----------------------------------
    sq_kernel<<<(NROWS + 255) / 256, 256>>>(x);
    wtmp_kernel<<<(3 * 128 + 255) / 256, 256>>>(w1, 3, 64);
    hh3_kernel<<<NROWS, 128>>>(x);
    select3_kernel<<<NROWS / 4, 128>>>(x);
    edge_gather_kernel<<<NROWS, 64>>>(64);
    stats_reduce_kernel<<<dim3(4, NB), 256>>>(8, 4, (float)(NPTS * KNN * 16));
    edge_final_kernel<<<NROWS, 64>>>(64, 0, g1w, g1b);

    // ---------------- layers 2-4 ------------------------------------------
    struct LayerCfg {
        int coffin;   // input slice offset in g_ch/g_cl
        int C; int O;
        const float* w; const float* gw; const float* gb; int coff;
    };
    LayerCfg layers[3] = {
        { 0,   64,  64,  w2, g2w, g2b, 64  },
        { 64,  64,  128, w3, g3w, g3b, 128 },
        { 128, 128, 256, w4, g4w, g4b, 256 },
    };

    const int NTILES = (NPTS / 128) * (NPTS / 128 + 1) / 2;   // 136

    for (int l = 0; l < 3; l++) {
        const LayerCfg& L = layers[l];
        mmagemm_bf<true><<<dim3(NTILES, 1, NB), 256, GEMM_SMEM>>>(
            pCh + L.coffin, pCl + L.coffin, 512, (size_t)NPTS * 512,
            pCh + L.coffin, pCl + L.coffin, 512, (size_t)NPTS * 512,
            pGram, NPTS, (size_t)NPTS * NPTS, L.C);
        select_gram_kernel<<<NROWS / 4, 128>>>();
        wtmp_bf_kernel<<<(2 * L.O * L.C + 255) / 256, 256>>>(L.w, L.C, L.O);
        mmagemm_bf<false><<<dim3(2 * L.O / 128, NROWS / 128, 1), 256, GEMM_SMEM>>>(
            pCh + L.coffin, pCl + L.coffin, 512, 0,
            pWth, pWtl, L.C, 0,
            pHH, 2 * L.O, 0, L.C);
        edge_gather_kernel<<<NROWS, L.O>>>(L.O);
        stats_reduce_kernel<<<dim3(4, NB), 256>>>(8, 4, (float)(NPTS * KNN * (L.O / 4)));
        edge_final_kernel<<<NROWS, L.O>>>(L.O, L.coff, L.gw, L.gb);
    }

    // mid: hm = concat @ wm^T  (16384 x 512 -> 1024)
    mmagemm_bf<false><<<dim3(1024 / 128, NROWS / 128, 1), 256, GEMM_SMEM>>>(
        pCh, pCl, 512, 0, pWmh, pWml, 512, 0, pHm, 1024, 0, 512);
    seq_stats_kernel<<<NROWS, 256>>>();
    stats_reduce_kernel<<<dim3(16, NB), 256>>>(32, 16, (float)(NPTS * 64));
    seq_max_part<<<dim3(4, NB, 8), 256>>>(gmw, gmb);
    seq_max_combine<<<dim3(4, NB), 256>>>();

    // head MLP
    mlp_kernel<<<NB, 256>>>(fc1w, fc1b, ln1w, ln1b,
                            fc2w, fc2b, ln2w, ln2b,
                            fc3w, fc3b, ln3w, ln3b,
                            fc4w, fc4b, out);
}